// round 2
// baseline (speedup 1.0000x reference)
#include <cuda_runtime.h>

// out[t,s] = sum_{k<=t} sum_a A[k,s,a] * us[t-k,a]
// GEMM view: out^T[S,T] = A_r[S, H*NA] @ Ushift[H*NA, T],
//            Ushift[(k,a),t] = (t>=k) ? us[t-k,a] : 0
//
// Split-K over KSPLIT=16 interleaved k-groups (CTA g owns k = g+16m).
// Grid: 8 s-tiles x 16 k-groups = 128 CTAs (one wave on 148 SMs).
// CTA tile: 128 s x 128 t, BK=32 (single k per chunk -> contiguous A rows).
// 256 threads, 8x8 register micro-tiles. Warp-uniform causal skip:
// warp's t-chunk (16 t) is all-dead when k >= tbase+16. t-chunks are
// permuted {0,1,2,3,7,6,5,4} across warps so each SMSP's warp pair
// (w, w+4) has equal live work (9/16 of full).
// Deterministic split-K: partials to __device__ scratch, then reduce.

#define S_DIM   1024
#define NA_DIM  512
#define H_DIM   128
#define KSPLIT  16
#define BK      32
#define PAD     132
#define NITER   128   // 8 m-steps * 16 a-chunks

__device__ float g_partial[KSPLIT * H_DIM * S_DIM];   // 8 MB scratch

__global__ __launch_bounds__(256, 1)
void cg_kernel(const float* __restrict__ us, const float* __restrict__ A)
{
    __shared__ float Asm[BK][PAD];
    __shared__ float Usm[BK][PAD];

    const int s0 = blockIdx.x * 128;
    const int g  = blockIdx.y;

    const int tid  = threadIdx.x;
    const int wid  = tid >> 5;
    const int lane = tid & 31;
    const int ls   = lane & 15;   // s sub-block 0..15
    const int lt   = lane >> 4;   // t sub-block 0..1

    // SMSP-balanced t-chunk permutation: pairs (w, w+4) sum to 9
    const int tchunk = (wid < 4) ? wid : (11 - wid);
    const int tbase  = tchunk << 4;

    float acc[8][8];
#pragma unroll
    for (int i = 0; i < 8; i++)
#pragma unroll
        for (int j = 0; j < 8; j++) acc[i][j] = 0.f;

    // ---------------- prologue: load tile 0 into smem ----------------
    {
        const int k0 = g;           // it=0 -> m=0, a0=0
#pragma unroll
        for (int j = 0; j < 4; j++) {
            int idx = tid + (j << 8);
            int ss  = idx >> 3;           // 0..127 (doubles as t for U)
            int aa  = (idx & 7) << 2;     // 0,4,...,28
            float4 va = *reinterpret_cast<const float4*>(
                &A[(((long)k0 << 10) + (s0 + ss)) * 512 + aa]);
            float4 vu = (ss >= k0)
                ? *reinterpret_cast<const float4*>(&us[(ss - k0) * 512 + aa])
                : make_float4(0.f, 0.f, 0.f, 0.f);
            Asm[aa + 0][ss] = va.x; Asm[aa + 1][ss] = va.y;
            Asm[aa + 2][ss] = va.z; Asm[aa + 3][ss] = va.w;
            Usm[aa + 0][ss] = vu.x; Usm[aa + 1][ss] = vu.y;
            Usm[aa + 2][ss] = vu.z; Usm[aa + 3][ss] = vu.w;
        }
    }
    __syncthreads();

    // ---------------- main loop ----------------
    for (int it = 0; it < NITER; it++) {
        const int kk = g + ((it >> 4) << 4);   // k of tile currently in smem

        // register-prefetch tile it+1
        float4 na[4], nu[4];
        if (it + 1 < NITER) {
            const int k2  = g + (((it + 1) >> 4) << 4);
            const int a02 = ((it + 1) & 15) << 5;
#pragma unroll
            for (int j = 0; j < 4; j++) {
                int idx = tid + (j << 8);
                int ss  = idx >> 3;
                int aa  = (idx & 7) << 2;
                na[j] = *reinterpret_cast<const float4*>(
                    &A[(((long)k2 << 10) + (s0 + ss)) * 512 + a02 + aa]);
                nu[j] = (ss >= k2)
                    ? *reinterpret_cast<const float4*>(&us[(ss - k2) * 512 + a02 + aa])
                    : make_float4(0.f, 0.f, 0.f, 0.f);
            }
        }

        // causal warp-uniform skip: all 16 t of this warp dead if kk >= tbase+16
        if (kk < tbase + 16) {
#pragma unroll 8
            for (int aa = 0; aa < BK; aa++) {
                float4 a0v = *reinterpret_cast<const float4*>(&Asm[aa][ls << 3]);
                float4 a1v = *reinterpret_cast<const float4*>(&Asm[aa][(ls << 3) + 4]);
                float4 u0v = *reinterpret_cast<const float4*>(&Usm[aa][tbase + (lt << 3)]);
                float4 u1v = *reinterpret_cast<const float4*>(&Usm[aa][tbase + (lt << 3) + 4]);
                float av[8] = {a0v.x, a0v.y, a0v.z, a0v.w, a1v.x, a1v.y, a1v.z, a1v.w};
                float uv[8] = {u0v.x, u0v.y, u0v.z, u0v.w, u1v.x, u1v.y, u1v.z, u1v.w};
#pragma unroll
                for (int i = 0; i < 8; i++)
#pragma unroll
                    for (int j = 0; j < 8; j++)
                        acc[i][j] += av[i] * uv[j];
            }
        }
        __syncthreads();

        if (it + 1 < NITER) {
#pragma unroll
            for (int j = 0; j < 4; j++) {
                int idx = tid + (j << 8);
                int ss  = idx >> 3;
                int aa  = (idx & 7) << 2;
                Asm[aa + 0][ss] = na[j].x; Asm[aa + 1][ss] = na[j].y;
                Asm[aa + 2][ss] = na[j].z; Asm[aa + 3][ss] = na[j].w;
                Usm[aa + 0][ss] = nu[j].x; Usm[aa + 1][ss] = nu[j].y;
                Usm[aa + 2][ss] = nu[j].z; Usm[aa + 3][ss] = nu[j].w;
            }
        }
        __syncthreads();
    }

    // ---------------- epilogue: write partials ----------------
    float* pp = g_partial + (long)g * (H_DIM * S_DIM);
#pragma unroll
    for (int j = 0; j < 8; j++) {
        int t = tbase + (lt << 3) + j;
        float* row = pp + t * S_DIM + s0 + (ls << 3);
        *reinterpret_cast<float4*>(row) =
            make_float4(acc[0][j], acc[1][j], acc[2][j], acc[3][j]);
        *reinterpret_cast<float4*>(row + 4) =
            make_float4(acc[4][j], acc[5][j], acc[6][j], acc[7][j]);
    }
}

__global__ __launch_bounds__(256)
void reduce_kernel(float* __restrict__ out)
{
    int i = blockIdx.x * 256 + threadIdx.x;   // 0..131071
    float s = 0.f;
#pragma unroll
    for (int gg = 0; gg < KSPLIT; gg++)
        s += g_partial[gg * (H_DIM * S_DIM) + i];
    out[i] = s;
}

extern "C" void kernel_launch(void* const* d_in, const int* in_sizes, int n_in,
                              void* d_out, int out_size)
{
    const float* us = (const float*)d_in[0];   // [128, 512]
    const float* A  = (const float*)d_in[1];   // [128, 1024, 512]
    if (n_in >= 2 && in_sizes[0] > in_sizes[1]) {  // defensive: us is the small one
        const float* t = us; us = A; A = t;
    }

    dim3 grid(S_DIM / 128, KSPLIT);
    cg_kernel<<<grid, 256>>>(us, A);
    reduce_kernel<<<(H_DIM * S_DIM) / 256, 256>>>((float*)d_out);
}

// round 7
// speedup vs baseline: 2.5891x; 2.5891x over previous
#include <cuda_runtime.h>
#include <cuda_fp16.h>
#include <cstdint>

// out[t,s] = sum_{k<=t} sum_a A[k,s,a] * us[t-k,a]
// GEMM: C[s,t] = sum_{k,a} A[k,s,a] * Upad[t+128-k, a]
// mma.sync.m16n8k16 fp16 (family-safe HMMA; tcgen05.ld unavailable on
// the harness's sm_103 PTX target). fp16 2-term split of A and U,
// 3 chains: Ah*Uh + Ah*Ul + Al*Uh  (error ~2^-22).
// Split-K=16, balanced k-sets; 8 s-tiles x 16 = 128 CTAs (one wave).
// CTA 128m x 128n, 8 warps (4m x 2n), warp n8-tiles interleaved for
// balanced causal skip (skip mma when k >= n+8). Double-buffered smem,
// cp.async for B, in-kernel fp32->fp16 split of A. Deterministic
// split-K partials + reduce.

#define KSPLIT 16
#define APITCH 80             // bytes per smem row (40 halves, conflict-spread)
#define ASTG   (128*APITCH)   // 10240 B per operand tile
#define STAGE  (4*ASTG)       // Ah Al Bh Bl
#define SMEMT  (2*STAGE)      // 81920 B dynamic smem

__device__ float  g_partial[KSPLIT*128*1024];  // [g][t][s]  8 MB
__device__ __half g_Uh[256*512];
__device__ __half g_Ul[256*512];

__global__ __launch_bounds__(256) void prep_kernel(const float* __restrict__ us)
{
    int i = blockIdx.x*256 + threadIdx.x;   // 0..131071 over [256][512]
    int r = i >> 9, a = i & 511;
    float x = (r >= 128) ? us[(r-128)*512 + a] : 0.f;
    __half h = __float2half_rn(x);
    __half l = __float2half_rn(x - __half2float(h));
    g_Uh[i] = h;
    g_Ul[i] = l;
}

__device__ __forceinline__ void ldmx4(uint32_t* r, uint32_t addr) {
    asm volatile("ldmatrix.sync.aligned.m8n8.x4.shared.b16 {%0,%1,%2,%3}, [%4];"
        : "=r"(r[0]), "=r"(r[1]), "=r"(r[2]), "=r"(r[3]) : "r"(addr));
}
__device__ __forceinline__ void mma16816(float* c, const uint32_t* a, const uint32_t* b) {
    asm volatile("mma.sync.aligned.m16n8k16.row.col.f32.f16.f16.f32 "
        "{%0,%1,%2,%3}, {%4,%5,%6,%7}, {%8,%9}, {%0,%1,%2,%3};"
        : "+f"(c[0]), "+f"(c[1]), "+f"(c[2]), "+f"(c[3])
        : "r"(a[0]), "r"(a[1]), "r"(a[2]), "r"(a[3]), "r"(b[0]), "r"(b[1]));
}
__device__ __forceinline__ void cpa16(uint32_t dst, const void* src) {
    asm volatile("cp.async.cg.shared.global [%0], [%1], 16;" :: "r"(dst), "l"(src));
}
__device__ __forceinline__ uint32_t packh(__half a, __half b) {
    return (uint32_t)__half_as_ushort(a) | ((uint32_t)__half_as_ushort(b) << 16);
}

__global__ __launch_bounds__(256, 1)
void mma_kernel(const float* __restrict__ A)
{
    extern __shared__ char smem[];
    const uint32_t smb = (uint32_t)__cvta_generic_to_shared(smem);

    const int tid  = threadIdx.x;
    const int wid  = tid >> 5;
    const int lane = tid & 31;
    const int wm   = wid & 3;     // 4 m-groups of 32
    const int ng   = wid >> 2;    // 2 interleaved n-groups
    const int s0   = blockIdx.x * 128;
    const int g    = blockIdx.y;

    // A loader indices: thread covers rows lrow+32j, fp32 k-offset lk4
    const int lrow = tid >> 3;          // 0..31
    const int lk4  = (tid & 7) * 4;     // 0..28
    // B loader: row r, which array (h/l)
    const int brow = tid >> 1;          // 0..127
    const int barr = tid & 1;

    // ldmatrix per-lane offsets (bytes within operand tile)
    const uint32_t aoff = (uint32_t)((wm*32 + (lane & 15)) * APITCH + (lane >> 4) * 16);
    const uint32_t boff = (uint32_t)((16*(lane >> 4) + 8*ng + (lane & 7)) * APITCH
                                     + ((lane >> 3) & 1) * 16);

    float acc[2][8][4];
#pragma unroll
    for (int im = 0; im < 2; im++)
#pragma unroll
        for (int j = 0; j < 8; j++)
#pragma unroll
            for (int c = 0; c < 4; c++) acc[im][j][c] = 0.f;

    // balanced k-set: jk even -> (jk/2)*32 + g, odd -> (jk/2)*32 + 31 - g
#define KOF(i) ( (((i) >> 4) & 1) ? ((((i) >> 5) << 5) + 31 - g) \
                                  : ((((i) >> 5) << 5) + g) )

    float rA[16];

    // ---- helpers as lambdas ----
    auto ldgA = [&](int i) {
        const int k  = KOF(i);
        const int a0 = (i & 15) << 5;
        const float* p = A + ((size_t)(k*1024 + s0 + lrow)) * 512 + a0 + lk4;
#pragma unroll
        for (int jj = 0; jj < 4; jj++) {
            float4 v = *reinterpret_cast<const float4*>(p + (size_t)jj * 32 * 512);
            rA[4*jj+0] = v.x; rA[4*jj+1] = v.y; rA[4*jj+2] = v.z; rA[4*jj+3] = v.w;
        }
    };
    auto stsA = [&](int buf) {
        char* dh = smem + buf*STAGE;
        char* dl = dh + ASTG;
#pragma unroll
        for (int jj = 0; jj < 4; jj++) {
            int row = lrow + 32*jj;
            __half h0 = __float2half_rn(rA[4*jj+0]);
            __half h1 = __float2half_rn(rA[4*jj+1]);
            __half h2 = __float2half_rn(rA[4*jj+2]);
            __half h3 = __float2half_rn(rA[4*jj+3]);
            __half l0 = __float2half_rn(rA[4*jj+0] - __half2float(h0));
            __half l1 = __float2half_rn(rA[4*jj+1] - __half2float(h1));
            __half l2 = __float2half_rn(rA[4*jj+2] - __half2float(h2));
            __half l3 = __float2half_rn(rA[4*jj+3] - __half2float(h3));
            uint2 hv = make_uint2(packh(h0, h1), packh(h2, h3));
            uint2 lv = make_uint2(packh(l0, l1), packh(l2, l3));
            *reinterpret_cast<uint2*>(dh + row*APITCH + lk4*2) = hv;
            *reinterpret_cast<uint2*>(dl + row*APITCH + lk4*2) = lv;
        }
    };
    auto cpB = [&](int i, int buf) {
        const int k  = KOF(i);
        const int a0 = (i & 15) << 5;
        const __half* src = (barr ? g_Ul : g_Uh) + (size_t)(brow + 128 - k) * 512 + a0;
        uint32_t dst = smb + buf*STAGE + (2 + barr)*ASTG + brow*APITCH;
#pragma unroll
        for (int c = 0; c < 4; c++)
            cpa16(dst + 16*c, src + 8*c);
    };

    // ---- prologue ----
    ldgA(0);
    cpB(0, 0);
    asm volatile("cp.async.commit_group;" ::: "memory");
    stsA(0);

    // ---- main loop ----
    for (int i = 0; i < 128; i++) {
        const int buf  = i & 1;
        const int k    = KOF(i);

        asm volatile("cp.async.wait_group 0;" ::: "memory");
        __syncthreads();

        const int inext = i + 1;
        if (inext < 128) {
            cpB(inext, inext & 1);
            asm volatile("cp.async.commit_group;" ::: "memory");
            ldgA(inext);
        }

        // causal liveness per warp n8-tile
        bool lv[8];
#pragma unroll
        for (int j = 0; j < 8; j++)
            lv[j] = (k < ((2*j + ng) << 3) + 8);

        const uint32_t base = smb + buf*STAGE;
#pragma unroll
        for (int kb = 0; kb < 2; kb++) {
            const uint32_t ko = kb * 32;      // 16 halves = 32 bytes
            uint32_t ah[2][4], al[2][4], uh[4][4], ul[4][4];
            ldmx4(ah[0], base + aoff + ko);
            ldmx4(ah[1], base + aoff + 1280 + ko);
#pragma unroll
            for (int p = 0; p < 4; p++)
                ldmx4(uh[p], base + 2*ASTG + boff + 2560*p + ko);
            // chain 1: Ah * Uh
#pragma unroll
            for (int im = 0; im < 2; im++)
#pragma unroll
                for (int j = 0; j < 8; j++)
                    if (lv[j]) mma16816(acc[im][j], ah[im], &uh[j >> 1][(j & 1) * 2]);
#pragma unroll
            for (int p = 0; p < 4; p++)
                ldmx4(ul[p], base + 3*ASTG + boff + 2560*p + ko);
            // chain 2: Ah * Ul
#pragma unroll
            for (int im = 0; im < 2; im++)
#pragma unroll
                for (int j = 0; j < 8; j++)
                    if (lv[j]) mma16816(acc[im][j], ah[im], &ul[j >> 1][(j & 1) * 2]);
            ldmx4(al[0], base + ASTG + aoff + ko);
            ldmx4(al[1], base + ASTG + aoff + 1280 + ko);
            // chain 3: Al * Uh
#pragma unroll
            for (int im = 0; im < 2; im++)
#pragma unroll
                for (int j = 0; j < 8; j++)
                    if (lv[j]) mma16816(acc[im][j], al[im], &uh[j >> 1][(j & 1) * 2]);
        }

        if (inext < 128)
            stsA(inext & 1);
    }

    // ---- epilogue: write split-K partials [g][t][s] ----
    float* pb = g_partial + (size_t)g * 131072;
    const int sidx = s0 + wm*32 + (lane >> 2);
#pragma unroll
    for (int im = 0; im < 2; im++) {
        const int sr = sidx + im*16;
#pragma unroll
        for (int j = 0; j < 8; j++) {
            const int n = ((2*j + ng) << 3) + (lane & 3) * 2;
            pb[(size_t)n      * 1024 + sr]     = acc[im][j][0];
            pb[(size_t)(n+1)  * 1024 + sr]     = acc[im][j][1];
            pb[(size_t)n      * 1024 + sr + 8] = acc[im][j][2];
            pb[(size_t)(n+1)  * 1024 + sr + 8] = acc[im][j][3];
        }
    }
}

__global__ __launch_bounds__(256) void reduce_kernel(float* __restrict__ out)
{
    int i = blockIdx.x*256 + threadIdx.x;   // 0..32767 float4s
    float4 s = make_float4(0.f, 0.f, 0.f, 0.f);
#pragma unroll
    for (int gg = 0; gg < KSPLIT; gg++) {
        float4 v = *reinterpret_cast<const float4*>(g_partial + (size_t)gg*131072 + (size_t)i*4);
        s.x += v.x; s.y += v.y; s.z += v.z; s.w += v.w;
    }
    reinterpret_cast<float4*>(out)[i] = s;
}

extern "C" void kernel_launch(void* const* d_in, const int* in_sizes, int n_in,
                              void* d_out, int out_size)
{
    const float* us = (const float*)d_in[0];   // [128, 512]
    const float* A  = (const float*)d_in[1];   // [128, 1024, 512]
    if (n_in >= 2 && in_sizes[0] > in_sizes[1]) {
        const float* t = us; us = A; A = t;
    }
    cudaFuncSetAttribute(mma_kernel, cudaFuncAttributeMaxDynamicSharedMemorySize, SMEMT);

    prep_kernel<<<512, 256>>>(us);
    mma_kernel<<<dim3(8, KSPLIT), 256, SMEMT>>>(A);
    reduce_kernel<<<128, 256>>>((float*)d_out);
}

// round 8
// speedup vs baseline: 3.2148x; 1.2417x over previous
#include <cuda_runtime.h>
#include <cuda_fp16.h>
#include <cstdint>

// out[t,s] = sum_{k<=t} sum_a A[k,s,a] * us[t-k,a]
// GEMM: C[s,t] = sum_{k,a} A[k,s,a] * Upad[t+128-k, a]
// mma.sync.m16n8k16 fp16 (family-safe HMMA). 2-chain scheme:
//   Ah*Uh + Ah*Ul   (A rounded to fp16; U split hi+lo)
// Error ~ Al*U ~ 2^-12.5 aggregate ≈ 2-4e-4 < 1e-3.
// Split-K=16, balanced k-sets; 8 s-tiles x 16 = 128 CTAs (one wave).
// CTA 128m x 128n, 8 warps (4m x 2n), interleaved warp n8-tiles for
// balanced causal skip; dead-tile skip on both MMA and B ldmatrix.
// Double-buffered smem (3 tiles/stage: Ah Bh Bl), cp.async for B,
// in-kernel fp32->fp16 round of A. Deterministic split-K + reduce.

#define KSPLIT 16
#define APITCH 80             // bytes per smem row (40 halves, conflict-spread)
#define ASTG   (128*APITCH)   // 10240 B per operand tile
#define STAGE  (3*ASTG)       // Ah Bh Bl
#define SMEMT  (2*STAGE)      // 61440 B dynamic smem

__device__ float  g_partial[KSPLIT*128*1024];  // [g][t][s]  8 MB
__device__ __half g_Uh[256*512];
__device__ __half g_Ul[256*512];

__global__ __launch_bounds__(256) void prep_kernel(const float* __restrict__ us)
{
    int i = blockIdx.x*256 + threadIdx.x;   // 0..131071 over [256][512]
    int r = i >> 9, a = i & 511;
    float x = (r >= 128) ? us[(r-128)*512 + a] : 0.f;
    __half h = __float2half_rn(x);
    __half l = __float2half_rn(x - __half2float(h));
    g_Uh[i] = h;
    g_Ul[i] = l;
}

__device__ __forceinline__ void ldmx4(uint32_t* r, uint32_t addr) {
    asm volatile("ldmatrix.sync.aligned.m8n8.x4.shared.b16 {%0,%1,%2,%3}, [%4];"
        : "=r"(r[0]), "=r"(r[1]), "=r"(r[2]), "=r"(r[3]) : "r"(addr));
}
__device__ __forceinline__ void mma16816(float* c, const uint32_t* a, const uint32_t* b) {
    asm volatile("mma.sync.aligned.m16n8k16.row.col.f32.f16.f16.f32 "
        "{%0,%1,%2,%3}, {%4,%5,%6,%7}, {%8,%9}, {%0,%1,%2,%3};"
        : "+f"(c[0]), "+f"(c[1]), "+f"(c[2]), "+f"(c[3])
        : "r"(a[0]), "r"(a[1]), "r"(a[2]), "r"(a[3]), "r"(b[0]), "r"(b[1]));
}
__device__ __forceinline__ void cpa16(uint32_t dst, const void* src) {
    asm volatile("cp.async.cg.shared.global [%0], [%1], 16;" :: "r"(dst), "l"(src));
}
__device__ __forceinline__ uint32_t packh(__half a, __half b) {
    return (uint32_t)__half_as_ushort(a) | ((uint32_t)__half_as_ushort(b) << 16);
}

__global__ __launch_bounds__(256, 1)
void mma_kernel(const float* __restrict__ A)
{
    extern __shared__ char smem[];
    const uint32_t smb = (uint32_t)__cvta_generic_to_shared(smem);

    const int tid  = threadIdx.x;
    const int wid  = tid >> 5;
    const int lane = tid & 31;
    const int wm   = wid & 3;     // 4 m-groups of 32
    const int ng   = wid >> 2;    // 2 interleaved n-groups
    const int s0   = blockIdx.x * 128;
    const int g    = blockIdx.y;

    // A loader indices
    const int lrow = tid >> 3;          // 0..31
    const int lk4  = (tid & 7) * 4;     // 0..28
    // B loader
    const int brow = tid >> 1;          // 0..127
    const int barr = tid & 1;

    // ldmatrix per-lane offsets (bytes within operand tile)
    const uint32_t aoff = (uint32_t)((wm*32 + (lane & 15)) * APITCH + (lane >> 4) * 16);
    const uint32_t boff = (uint32_t)((16*(lane >> 4) + 8*ng + (lane & 7)) * APITCH
                                     + ((lane >> 3) & 1) * 16);

    float acc[2][8][4];
#pragma unroll
    for (int im = 0; im < 2; im++)
#pragma unroll
        for (int j = 0; j < 8; j++)
#pragma unroll
            for (int c = 0; c < 4; c++) acc[im][j][c] = 0.f;

    // balanced k-set: pairs (g, 31-g) within each block of 32
#define KOF(i) ( (((i) >> 4) & 1) ? ((((i) >> 5) << 5) + 31 - g) \
                                  : ((((i) >> 5) << 5) + g) )

    float rA[16];

    auto ldgA = [&](int i) {
        const int k  = KOF(i);
        const int a0 = (i & 15) << 5;
        const float* p = A + ((size_t)(k*1024 + s0 + lrow)) * 512 + a0 + lk4;
#pragma unroll
        for (int jj = 0; jj < 4; jj++) {
            float4 v = *reinterpret_cast<const float4*>(p + (size_t)jj * 32 * 512);
            rA[4*jj+0] = v.x; rA[4*jj+1] = v.y; rA[4*jj+2] = v.z; rA[4*jj+3] = v.w;
        }
    };
    auto stsA = [&](int buf) {
        char* dh = smem + buf*STAGE;
#pragma unroll
        for (int jj = 0; jj < 4; jj++) {
            int row = lrow + 32*jj;
            uint2 hv = make_uint2(
                packh(__float2half_rn(rA[4*jj+0]), __float2half_rn(rA[4*jj+1])),
                packh(__float2half_rn(rA[4*jj+2]), __float2half_rn(rA[4*jj+3])));
            *reinterpret_cast<uint2*>(dh + row*APITCH + lk4*2) = hv;
        }
    };
    auto cpB = [&](int i, int buf) {
        const int k  = KOF(i);
        const int a0 = (i & 15) << 5;
        const __half* src = (barr ? g_Ul : g_Uh) + (size_t)(brow + 128 - k) * 512 + a0;
        uint32_t dst = smb + buf*STAGE + (1 + barr)*ASTG + brow*APITCH;
#pragma unroll
        for (int c = 0; c < 4; c++)
            cpa16(dst + 16*c, src + 8*c);
    };

    // ---- prologue ----
    ldgA(0);
    cpB(0, 0);
    asm volatile("cp.async.commit_group;" ::: "memory");
    stsA(0);

    // ---- main loop ----
    for (int i = 0; i < 128; i++) {
        const int buf  = i & 1;
        const int k    = KOF(i);

        asm volatile("cp.async.wait_group 0;" ::: "memory");
        __syncthreads();

        const int inext = i + 1;
        if (inext < 128) {
            cpB(inext, inext & 1);
            asm volatile("cp.async.commit_group;" ::: "memory");
            ldgA(inext);
        }

        // causal liveness: n8-tile j covers n in [(2j+ng)*8, +8)
        bool lv[8];
#pragma unroll
        for (int j = 0; j < 8; j++)
            lv[j] = (k < ((2*j + ng) << 3) + 8);
        // B x4-tile p feeds j = 2p, 2p+1; live iff lv[2p+1] (lv monotone inc in j)
        bool lp[4];
#pragma unroll
        for (int p = 0; p < 4; p++)
            lp[p] = lv[2*p + 1];

        const uint32_t base = smb + buf*STAGE;
#pragma unroll
        for (int kb = 0; kb < 2; kb++) {
            const uint32_t ko = kb * 32;
            uint32_t ah[2][4], uh[4][4], ul[4][4];
            ldmx4(ah[0], base + aoff + ko);
            ldmx4(ah[1], base + aoff + 1280 + ko);
#pragma unroll
            for (int p = 0; p < 4; p++)
                if (lp[p]) ldmx4(uh[p], base + 1*ASTG + boff + 2560*p + ko);
            // chain 1: Ah * Uh
#pragma unroll
            for (int im = 0; im < 2; im++)
#pragma unroll
                for (int j = 0; j < 8; j++)
                    if (lv[j]) mma16816(acc[im][j], ah[im], &uh[j >> 1][(j & 1) * 2]);
#pragma unroll
            for (int p = 0; p < 4; p++)
                if (lp[p]) ldmx4(ul[p], base + 2*ASTG + boff + 2560*p + ko);
            // chain 2: Ah * Ul
#pragma unroll
            for (int im = 0; im < 2; im++)
#pragma unroll
                for (int j = 0; j < 8; j++)
                    if (lv[j]) mma16816(acc[im][j], ah[im], &ul[j >> 1][(j & 1) * 2]);
        }

        if (inext < 128)
            stsA(inext & 1);
    }

    // ---- epilogue: write split-K partials [g][t][s] ----
    float* pb = g_partial + (size_t)g * 131072;
    const int sidx = s0 + wm*32 + (lane >> 2);
#pragma unroll
    for (int im = 0; im < 2; im++) {
        const int sr = sidx + im*16;
#pragma unroll
        for (int j = 0; j < 8; j++) {
            const int n = ((2*j + ng) << 3) + (lane & 3) * 2;
            pb[(size_t)n      * 1024 + sr]     = acc[im][j][0];
            pb[(size_t)(n+1)  * 1024 + sr]     = acc[im][j][1];
            pb[(size_t)n      * 1024 + sr + 8] = acc[im][j][2];
            pb[(size_t)(n+1)  * 1024 + sr + 8] = acc[im][j][3];
        }
    }
}

__global__ __launch_bounds__(256) void reduce_kernel(float* __restrict__ out)
{
    int i = blockIdx.x*256 + threadIdx.x;   // 0..32767 float4s
    float4 s = make_float4(0.f, 0.f, 0.f, 0.f);
#pragma unroll
    for (int gg = 0; gg < KSPLIT; gg++) {
        float4 v = *reinterpret_cast<const float4*>(g_partial + (size_t)gg*131072 + (size_t)i*4);
        s.x += v.x; s.y += v.y; s.z += v.z; s.w += v.w;
    }
    reinterpret_cast<float4*>(out)[i] = s;
}

extern "C" void kernel_launch(void* const* d_in, const int* in_sizes, int n_in,
                              void* d_out, int out_size)
{
    const float* us = (const float*)d_in[0];   // [128, 512]
    const float* A  = (const float*)d_in[1];   // [128, 1024, 512]
    if (n_in >= 2 && in_sizes[0] > in_sizes[1]) {
        const float* t = us; us = A; A = t;
    }
    cudaFuncSetAttribute(mma_kernel, cudaFuncAttributeMaxDynamicSharedMemorySize, SMEMT);

    prep_kernel<<<512, 256>>>(us);
    mma_kernel<<<dim3(8, KSPLIT), 256, SMEMT>>>(A);
    reduce_kernel<<<128, 256>>>((float*)d_out);
}

// round 9
// speedup vs baseline: 6.0916x; 1.8949x over previous
#include <cuda_runtime.h>
#include <cuda_fp16.h>
#include <cstdint>

// out[t,s] = sum_{k<=t} sum_a A[k,s,a] * us[t-k,a]
// GEMM: C[s,t] = sum_{k,a} A[k,s,a] * Upad[t+128-k, a]
// mma.sync.m16n8k16, SINGLE fp16 chain: rn(A) * rn(U).
// Error = Al*U (+) Ah*Ul ~ sqrt(2)*2e-4 ~ 2.9e-4 < 1e-3 (measured R8:
// the Al*U half alone was 2.03e-4).
// Split-K=16, balanced k-sets {g,31-g,32+g,...}; 8 s-tiles x 16 = 128
// CTAs (one wave). CTA 128m x 128n, 8 warps (4m x 2n interleaved n8
// tiles), causal skip on MMA + B ldmatrix. K=64 per iteration (64
// iters), double-buffered smem, 128B rows with XOR-unit swizzle
// (conflict-free ldmatrix). cp.async for B, in-kernel fp32->fp16 of A.
// Deterministic split-K partials + reduce.

#define KSPLIT 16
#define ASTG   16384          // 128 rows x 128 B (64 halves)
#define STAGE  (2*ASTG)       // A, B
#define SMEMT  (2*STAGE)      // 65536 B

__device__ float  g_partial[KSPLIT*128*1024];  // [g][t][s]  8 MB
__device__ __half g_Uf[256*512];

__global__ __launch_bounds__(256) void prep_kernel(const float* __restrict__ us)
{
    int i = blockIdx.x*256 + threadIdx.x;   // 0..131071 over [256][512]
    int r = i >> 9, a = i & 511;
    float x = (r >= 128) ? us[(r-128)*512 + a] : 0.f;
    g_Uf[i] = __float2half_rn(x);
}

__device__ __forceinline__ void ldmx4(uint32_t* r, uint32_t addr) {
    asm volatile("ldmatrix.sync.aligned.m8n8.x4.shared.b16 {%0,%1,%2,%3}, [%4];"
        : "=r"(r[0]), "=r"(r[1]), "=r"(r[2]), "=r"(r[3]) : "r"(addr));
}
__device__ __forceinline__ void mma16816(float* c, const uint32_t* a, const uint32_t* b) {
    asm volatile("mma.sync.aligned.m16n8k16.row.col.f32.f16.f16.f32 "
        "{%0,%1,%2,%3}, {%4,%5,%6,%7}, {%8,%9}, {%0,%1,%2,%3};"
        : "+f"(c[0]), "+f"(c[1]), "+f"(c[2]), "+f"(c[3])
        : "r"(a[0]), "r"(a[1]), "r"(a[2]), "r"(a[3]), "r"(b[0]), "r"(b[1]));
}
__device__ __forceinline__ void cpa16(uint32_t dst, const void* src) {
    asm volatile("cp.async.cg.shared.global [%0], [%1], 16;" :: "r"(dst), "l"(src));
}
__device__ __forceinline__ uint32_t packh(__half a, __half b) {
    return (uint32_t)__half_as_ushort(a) | ((uint32_t)__half_as_ushort(b) << 16);
}

__global__ __launch_bounds__(256, 1)
void mma_kernel(const float* __restrict__ A)
{
    extern __shared__ char smem[];
    const uint32_t smb = (uint32_t)__cvta_generic_to_shared(smem);

    const int tid  = threadIdx.x;
    const int wid  = tid >> 5;
    const int lane = tid & 31;
    const int wm   = wid & 3;     // 4 m-groups of 32
    const int ng   = wid >> 2;    // 2 interleaved n-groups
    const int s0   = blockIdx.x * 128;
    const int g    = blockIdx.y;

    // A loader: lanes 0-15 cover one 256B row chunk; 8 rows per thread
    const int rowgrp = tid >> 4;        // 0..15
    const int lane16 = tid & 15;
    // B loader: 2 threads per row
    const int brow = tid >> 1;          // 0..127
    const int bhalf = tid & 1;          // which 4-unit half of the row

    // ldmatrix lane geometry (swizzled 16B-unit addressing)
    const int arow  = wm*32 + (lane & 15);          // + 16*im
    const int axor  = arow & 7;
    const int asel  = lane >> 4;                    // k-unit lo/hi
    const int browl = 8*ng + (lane & 7) + 16*((lane >> 4) & 1);  // + 32*p
    const int bxor  = lane & 7;
    const int bsel  = (lane >> 3) & 1;

    float acc[2][8][4];
#pragma unroll
    for (int im = 0; im < 2; im++)
#pragma unroll
        for (int j = 0; j < 8; j++)
#pragma unroll
            for (int c = 0; c < 4; c++) acc[im][j][c] = 0.f;

    // 64 iterations: kk = i>>3 (8 k-values), a0 = (i&7)*64
#define KOF(i) ( (((i) >> 3) & 1) ? ((((i) >> 4) << 5) + 31 - g) \
                                  : ((((i) >> 4) << 5) + g) )

    float rA[32];

    auto ldgA = [&](int i) {
        const int k  = KOF(i);
        const int a0 = (i & 7) << 6;
#pragma unroll
        for (int jj = 0; jj < 8; jj++) {
            const int grow = s0 + rowgrp + 16*jj;
            float4 v = *reinterpret_cast<const float4*>(
                A + ((size_t)k*1024 + grow)*512 + a0 + lane16*4);
            rA[4*jj+0] = v.x; rA[4*jj+1] = v.y; rA[4*jj+2] = v.z; rA[4*jj+3] = v.w;
        }
    };
    auto stsA = [&](int buf) {
        const uint32_t bb = smb + buf*STAGE;
        const int unit = lane16 >> 1;
        const int sub  = (lane16 & 1) * 8;
#pragma unroll
        for (int jj = 0; jj < 8; jj++) {
            const int row = rowgrp + 16*jj;
            uint2 hv = make_uint2(
                packh(__float2half_rn(rA[4*jj+0]), __float2half_rn(rA[4*jj+1])),
                packh(__float2half_rn(rA[4*jj+2]), __float2half_rn(rA[4*jj+3])));
            *reinterpret_cast<uint2*>(smem + buf*STAGE + row*128 +
                                      (((unit) ^ (row & 7)) << 4) + sub) = hv;
        }
        (void)bb;
    };
    auto cpB = [&](int i, int buf) {
        const int k  = KOF(i);
        const int a0 = (i & 7) << 6;
        const __half* src = g_Uf + (size_t)(brow + 128 - k)*512 + a0;
        const uint32_t dst = smb + buf*STAGE + ASTG + brow*128;
        const int rx = brow & 7;
#pragma unroll
        for (int c = 0; c < 4; c++) {
            const int u = bhalf*4 + c;
            cpa16(dst + ((u ^ rx) << 4), src + u*8);
        }
    };

    // ---- prologue ----
    ldgA(0);
    cpB(0, 0);
    asm volatile("cp.async.commit_group;" ::: "memory");
    stsA(0);

    // ---- main loop (64 iterations, K=64 each) ----
    for (int i = 0; i < 64; i++) {
        const int buf = i & 1;
        const int k   = KOF(i);

        asm volatile("cp.async.wait_group 0;" ::: "memory");
        __syncthreads();

        const int inext = i + 1;
        if (inext < 64) {
            cpB(inext, inext & 1);
            asm volatile("cp.async.commit_group;" ::: "memory");
            ldgA(inext);
        }

        // causal liveness: n8-tile j covers n in [(2j+ng)*8, +8)
        bool lv[8];
#pragma unroll
        for (int j = 0; j < 8; j++)
            lv[j] = (k < ((2*j + ng) << 3) + 8);
        bool lp[4];
#pragma unroll
        for (int p = 0; p < 4; p++)
            lp[p] = lv[2*p + 1];      // lv monotone increasing in j

        const uint32_t ab = smb + buf*STAGE + arow*128;
        const uint32_t bb = smb + buf*STAGE + ASTG + browl*128;
#pragma unroll
        for (int kb = 0; kb < 4; kb++) {
            uint32_t ah[2][4], uf[4][4];
            const int au = 2*kb + asel;
            ldmx4(ah[0], ab +        ((au ^ axor) << 4));
            ldmx4(ah[1], ab + 2048 + ((au ^ axor) << 4));
            const int bu = 2*kb + bsel;
            const uint32_t bsw = (uint32_t)((bu ^ bxor) << 4);
#pragma unroll
            for (int p = 0; p < 4; p++)
                if (lp[p]) ldmx4(uf[p], bb + p*4096 + bsw);
#pragma unroll
            for (int im = 0; im < 2; im++)
#pragma unroll
                for (int j = 0; j < 8; j++)
                    if (lv[j]) mma16816(acc[im][j], ah[im], &uf[j >> 1][(j & 1) * 2]);
        }

        if (inext < 64)
            stsA(inext & 1);
    }

    // ---- epilogue: write split-K partials [g][t][s] ----
    float* pb = g_partial + (size_t)g * 131072;
    const int sidx = s0 + wm*32 + (lane >> 2);
#pragma unroll
    for (int im = 0; im < 2; im++) {
        const int sr = sidx + im*16;
#pragma unroll
        for (int j = 0; j < 8; j++) {
            const int n = ((2*j + ng) << 3) + (lane & 3) * 2;
            pb[(size_t)n      * 1024 + sr]     = acc[im][j][0];
            pb[(size_t)(n+1)  * 1024 + sr]     = acc[im][j][1];
            pb[(size_t)n      * 1024 + sr + 8] = acc[im][j][2];
            pb[(size_t)(n+1)  * 1024 + sr + 8] = acc[im][j][3];
        }
    }
}

__global__ __launch_bounds__(256) void reduce_kernel(float* __restrict__ out)
{
    int i = blockIdx.x*256 + threadIdx.x;   // 0..32767 float4s
    float4 s = make_float4(0.f, 0.f, 0.f, 0.f);
#pragma unroll
    for (int gg = 0; gg < KSPLIT; gg++) {
        float4 v = *reinterpret_cast<const float4*>(g_partial + (size_t)gg*131072 + (size_t)i*4);
        s.x += v.x; s.y += v.y; s.z += v.z; s.w += v.w;
    }
    reinterpret_cast<float4*>(out)[i] = s;
}

extern "C" void kernel_launch(void* const* d_in, const int* in_sizes, int n_in,
                              void* d_out, int out_size)
{
    const float* us = (const float*)d_in[0];   // [128, 512]
    const float* A  = (const float*)d_in[1];   // [128, 1024, 512]
    if (n_in >= 2 && in_sizes[0] > in_sizes[1]) {
        const float* t = us; us = A; A = t;
    }
    cudaFuncSetAttribute(mma_kernel, cudaFuncAttributeMaxDynamicSharedMemorySize, SMEMT);

    prep_kernel<<<512, 256>>>(us);
    mma_kernel<<<dim3(8, KSPLIT), 256, SMEMT>>>(A);
    reduce_kernel<<<128, 256>>>((float*)d_out);
}

// round 10
// speedup vs baseline: 6.5349x; 1.0728x over previous
#include <cuda_runtime.h>
#include <cuda_fp16.h>
#include <cstdint>

// out[t,s] = sum_{k<=t} sum_a A[k,s,a] * us[t-k,a]
// GEMM: C[s,t] = sum_{k,a} A[k,s,a] * Upad[t+128-k, a]
// mma.sync.m16n8k16, single fp16 chain (rel_err ~2.7e-4 measured).
// Split-K=16, balanced k-sets; 128 CTAs (one wave). CTA 128m x 128n,
// 8 warps (4m x 2n interleaved n8 tiles), causal skip on MMA+ldmatrix.
// R10: 2-iteration A pipeline (LDG at iter i for use at i+2; fp32->fp16
// convert deferred to end of body so LDG latency hides under MMA; STS
// from packed regs at top of next iter). Triple-buffered B via cp.async
// (wait_group 1 keeps one group in flight). 128B rows + XOR swizzle.
// Deterministic split-K partials + reduce.

#define KSPLIT 16
#define ATILE  16384          // 128 rows x 128 B
#define BOFF0  (2*ATILE)      // B region after 2 A buffers
#define SMEMT  (2*ATILE + 3*ATILE)   // 81920 B

__device__ float  g_partial[KSPLIT*128*1024];  // [g][t][s]  8 MB
__device__ __half g_Uf[256*512];

__global__ __launch_bounds__(256) void prep_kernel(const float* __restrict__ us)
{
    int i = blockIdx.x*256 + threadIdx.x;   // 0..131071 over [256][512]
    int r = i >> 9, a = i & 511;
    float x = (r >= 128) ? us[(r-128)*512 + a] : 0.f;
    g_Uf[i] = __float2half_rn(x);
}

__device__ __forceinline__ void ldmx4(uint32_t* r, uint32_t addr) {
    asm volatile("ldmatrix.sync.aligned.m8n8.x4.shared.b16 {%0,%1,%2,%3}, [%4];"
        : "=r"(r[0]), "=r"(r[1]), "=r"(r[2]), "=r"(r[3]) : "r"(addr));
}
__device__ __forceinline__ void mma16816(float* c, const uint32_t* a, const uint32_t* b) {
    asm volatile("mma.sync.aligned.m16n8k16.row.col.f32.f16.f16.f32 "
        "{%0,%1,%2,%3}, {%4,%5,%6,%7}, {%8,%9}, {%0,%1,%2,%3};"
        : "+f"(c[0]), "+f"(c[1]), "+f"(c[2]), "+f"(c[3])
        : "r"(a[0]), "r"(a[1]), "r"(a[2]), "r"(a[3]), "r"(b[0]), "r"(b[1]));
}
__device__ __forceinline__ void cpa16(uint32_t dst, const void* src) {
    asm volatile("cp.async.cg.shared.global [%0], [%1], 16;" :: "r"(dst), "l"(src));
}
__device__ __forceinline__ uint32_t packh(float a, float b) {
    __half2 h = __floats2half2_rn(a, b);
    return *reinterpret_cast<uint32_t*>(&h);
}

__global__ __launch_bounds__(256, 1)
void mma_kernel(const float* __restrict__ A)
{
    extern __shared__ char smem[];
    const uint32_t smb = (uint32_t)__cvta_generic_to_shared(smem);

    const int tid  = threadIdx.x;
    const int wid  = tid >> 5;
    const int lane = tid & 31;
    const int wm   = wid & 3;     // 4 m-groups of 32
    const int ng   = wid >> 2;    // 2 interleaved n-groups
    const int s0   = blockIdx.x * 128;
    const int g    = blockIdx.y;

    // A loader: 16 lanes span one 256B (64-float) chunk; 8 rows/thread
    const int rowgrp = tid >> 4;        // 0..15
    const int lane16 = tid & 15;
    // B loader: 2 threads per row
    const int brow  = tid >> 1;         // 0..127
    const int bhalf = tid & 1;

    // ldmatrix lane geometry (16B-unit XOR swizzle)
    const int arow  = wm*32 + (lane & 15);
    const int axor  = arow & 7;
    const int asel  = lane >> 4;
    const int browl = 8*ng + (lane & 7) + 16*((lane >> 4) & 1);
    const int bxor  = lane & 7;
    const int bsel  = (lane >> 3) & 1;

    float acc[2][8][4];
#pragma unroll
    for (int im = 0; im < 2; im++)
#pragma unroll
        for (int j = 0; j < 8; j++)
#pragma unroll
            for (int c = 0; c < 4; c++) acc[im][j][c] = 0.f;

#define KOF(i) ( (((i) >> 3) & 1) ? ((((i) >> 4) << 5) + 31 - g) \
                                  : ((((i) >> 4) << 5) + g) )

    float rF[32];     // raw fp32 A (loaded iter i, converted end of iter i)
    uint2 rH[8];      // packed fp16 A (written end of iter i, STS'd iter i+1)

    auto ldgF = [&](int i) {
        const int k  = KOF(i);
        const int a0 = (i & 7) << 6;
#pragma unroll
        for (int jj = 0; jj < 8; jj++) {
            const int grow = s0 + rowgrp + 16*jj;
            float4 v = *reinterpret_cast<const float4*>(
                A + ((size_t)k*1024 + grow)*512 + a0 + lane16*4);
            rF[4*jj+0] = v.x; rF[4*jj+1] = v.y; rF[4*jj+2] = v.z; rF[4*jj+3] = v.w;
        }
    };
    auto cvtA = [&]() {
#pragma unroll
        for (int jj = 0; jj < 8; jj++)
            rH[jj] = make_uint2(packh(rF[4*jj+0], rF[4*jj+1]),
                                packh(rF[4*jj+2], rF[4*jj+3]));
    };
    auto stsA = [&](int buf) {
        const int unit = lane16 >> 1;
        const int sub  = (lane16 & 1) * 8;
#pragma unroll
        for (int jj = 0; jj < 8; jj++) {
            const int row = rowgrp + 16*jj;
            *reinterpret_cast<uint2*>(smem + buf*ATILE + row*128 +
                                      ((unit ^ (row & 7)) << 4) + sub) = rH[jj];
        }
    };
    auto cpB = [&](int i, int buf) {
        const int k  = KOF(i);
        const int a0 = (i & 7) << 6;
        const __half* src = g_Uf + (size_t)(brow + 128 - k)*512 + a0;
        const uint32_t dst = smb + BOFF0 + buf*ATILE + brow*128;
        const int rx = brow & 7;
#pragma unroll
        for (int c = 0; c < 4; c++) {
            const int u = bhalf*4 + c;
            cpa16(dst + ((u ^ rx) << 4), src + u*8);
        }
    };

    // ---- prologue ----
    cpB(0, 0); asm volatile("cp.async.commit_group;" ::: "memory");
    cpB(1, 1); asm volatile("cp.async.commit_group;" ::: "memory");
    ldgF(0); cvtA(); stsA(0);
    ldgF(1); cvtA();               // rH = A(1)

    // ---- main loop (64 iterations, K=64 each) ----
    for (int i = 0; i < 64; i++) {
        const int abuf = i & 1;
        const int bbuf = i % 3;
        const int k    = KOF(i);

        if (i < 63) asm volatile("cp.async.wait_group 1;" ::: "memory");
        else        asm volatile("cp.async.wait_group 0;" ::: "memory");
        __syncthreads();

        if (i + 1 < 64) stsA((i + 1) & 1);     // from rH (ready since last iter)
        if (i + 2 < 64) {
            ldgF(i + 2);                       // raw LDGs; consumed at end of body
            cpB(i + 2, (i + 2) % 3);
            asm volatile("cp.async.commit_group;" ::: "memory");
        }

        // causal liveness: n8-tile j covers n in [(2j+ng)*8, +8)
        bool lv[8];
#pragma unroll
        for (int j = 0; j < 8; j++)
            lv[j] = (k < ((2*j + ng) << 3) + 8);
        bool lp[4];
#pragma unroll
        for (int p = 0; p < 4; p++)
            lp[p] = lv[2*p + 1];

        const uint32_t ab = smb + abuf*ATILE + arow*128;
        const uint32_t bb = smb + BOFF0 + bbuf*ATILE + browl*128;
#pragma unroll
        for (int kb = 0; kb < 4; kb++) {
            uint32_t ah[2][4], uf[4][4];
            const int au = 2*kb + asel;
            ldmx4(ah[0], ab +        ((au ^ axor) << 4));
            ldmx4(ah[1], ab + 2048 + ((au ^ axor) << 4));
            const int bu = 2*kb + bsel;
            const uint32_t bsw = (uint32_t)((bu ^ bxor) << 4);
#pragma unroll
            for (int p = 0; p < 4; p++)
                if (lp[p]) ldmx4(uf[p], bb + p*4096 + bsw);
#pragma unroll
            for (int im = 0; im < 2; im++)
#pragma unroll
                for (int j = 0; j < 8; j++)
                    if (lv[j]) mma16816(acc[im][j], ah[im], &uf[j >> 1][(j & 1) * 2]);
        }

        if (i + 2 < 64) cvtA();                // convert A(i+2) after latency hidden
    }

    // ---- epilogue: write split-K partials [g][t][s] ----
    float* pb = g_partial + (size_t)g * 131072;
    const int sidx = s0 + wm*32 + (lane >> 2);
#pragma unroll
    for (int im = 0; im < 2; im++) {
        const int sr = sidx + im*16;
#pragma unroll
        for (int j = 0; j < 8; j++) {
            const int n = ((2*j + ng) << 3) + (lane & 3) * 2;
            pb[(size_t)n      * 1024 + sr]     = acc[im][j][0];
            pb[(size_t)(n+1)  * 1024 + sr]     = acc[im][j][1];
            pb[(size_t)n      * 1024 + sr + 8] = acc[im][j][2];
            pb[(size_t)(n+1)  * 1024 + sr + 8] = acc[im][j][3];
        }
    }
}

__global__ __launch_bounds__(256) void reduce_kernel(float* __restrict__ out)
{
    int i = blockIdx.x*256 + threadIdx.x;   // 0..131071 floats
    float s = 0.f;
#pragma unroll
    for (int gg = 0; gg < KSPLIT; gg++)
        s += g_partial[(size_t)gg*131072 + i];
    out[i] = s;
}

extern "C" void kernel_launch(void* const* d_in, const int* in_sizes, int n_in,
                              void* d_out, int out_size)
{
    const float* us = (const float*)d_in[0];   // [128, 512]
    const float* A  = (const float*)d_in[1];   // [128, 1024, 512]
    if (n_in >= 2 && in_sizes[0] > in_sizes[1]) {
        const float* t = us; us = A; A = t;
    }
    cudaFuncSetAttribute(mma_kernel, cudaFuncAttributeMaxDynamicSharedMemorySize, SMEMT);

    prep_kernel<<<512, 256>>>(us);
    mma_kernel<<<dim3(8, KSPLIT), 256, SMEMT>>>(A);
    reduce_kernel<<<512, 256>>>((float*)d_out);
}

// round 11
// speedup vs baseline: 6.8238x; 1.0442x over previous
#include <cuda_runtime.h>
#include <cuda_fp16.h>
#include <cstdint>

// out[t,s] = sum_{k<=t} sum_a A[k,s,a] * us[t-k,a]
// GEMM: C[s,t] = sum_{k,a} A[k,s,a] * Upad[t+128-k, a]
// mma.sync.m16n8k16, single fp16 chain (rel_err ~2.7e-4 measured).
// R11: occupancy-2 / full-chip version. CTA 64m x 128n, grid = 16
// s-tiles x KSPLIT=18 = 288 CTAs on 296 slots (2 CTAs/SM, 148 SMs;
// was 128 CTAs = 20 idle SMs). Balanced reflected k-sets (+-2%).
// 8 warps (2m x 4n interleaved n8 tiles), causal skip on MMA+ldmatrix.
// K=64/iter, deferred-convert A pipeline, triple-buffered B cp.async,
// 128B rows + XOR swizzle. Deterministic split-K partials + reduce.
// Launch order [prep,dummy,dummy,mma,reduce] aligns ncu capture slot
// with mma_kernel.

#define KSPLIT 18
#define ATILE  8192           // 64 rows x 128 B
#define BTILE  16384          // 128 rows x 128 B
#define BOFF0  (2*ATILE)
#define SMEMT  (2*ATILE + 3*BTILE)   // 65536 B

__device__ float  g_partial[KSPLIT*128*1024];  // 9.4 MB
__device__ __half g_Uf[256*512];

__global__ __launch_bounds__(256) void prep_kernel(const float* __restrict__ us)
{
    int i = blockIdx.x*256 + threadIdx.x;   // 0..131071 over [256][512]
    int r = i >> 9, a = i & 511;
    float x = (r >= 128) ? us[(r-128)*512 + a] : 0.f;
    g_Uf[i] = __float2half_rn(x);
}

__global__ void dummy_kernel() {}

__device__ __forceinline__ void ldmx4(uint32_t* r, uint32_t addr) {
    asm volatile("ldmatrix.sync.aligned.m8n8.x4.shared.b16 {%0,%1,%2,%3}, [%4];"
        : "=r"(r[0]), "=r"(r[1]), "=r"(r[2]), "=r"(r[3]) : "r"(addr));
}
__device__ __forceinline__ void mma16816(float* c, const uint32_t* a, const uint32_t* b) {
    asm volatile("mma.sync.aligned.m16n8k16.row.col.f32.f16.f16.f32 "
        "{%0,%1,%2,%3}, {%4,%5,%6,%7}, {%8,%9}, {%0,%1,%2,%3};"
        : "+f"(c[0]), "+f"(c[1]), "+f"(c[2]), "+f"(c[3])
        : "r"(a[0]), "r"(a[1]), "r"(a[2]), "r"(a[3]), "r"(b[0]), "r"(b[1]));
}
__device__ __forceinline__ void cpa16(uint32_t dst, const void* src) {
    asm volatile("cp.async.cg.shared.global [%0], [%1], 16;" :: "r"(dst), "l"(src));
}
__device__ __forceinline__ uint32_t packh(float a, float b) {
    __half2 h = __floats2half2_rn(a, b);
    return *reinterpret_cast<uint32_t*>(&h);
}

// k-set for group g (0..17): t even: 36*(t/2)+g ; t odd: 36*((t+1)/2)-1-g ;
// t==7 (only g>=16): 143-g  -> covers all k in [0,128) once, cost-balanced.
__device__ __forceinline__ int kof(int g, int i) {
    const int t = i >> 3;
    if (t == 7) return 143 - g;
    return (t & 1) ? (36*((t+1) >> 1) - 1 - g) : (36*(t >> 1) + g);
}

__global__ __launch_bounds__(256, 2)
void mma_kernel(const float* __restrict__ A)
{
    extern __shared__ char smem[];
    const uint32_t smb = (uint32_t)__cvta_generic_to_shared(smem);

    const int tid  = threadIdx.x;
    const int wid  = tid >> 5;
    const int lane = tid & 31;
    const int wm   = wid & 1;     // 2 m-groups of 32
    const int ng   = wid >> 1;    // 4 interleaved n-groups
    const int s0   = blockIdx.x * 64;
    const int g    = blockIdx.y;
    const int NIT  = (g >= 16) ? 64 : 56;

    // A loader: 16 threads/row, rows rowgrp+16*jj (jj 0..3)
    const int rowgrp = tid >> 4;        // 0..15
    const int lane16 = tid & 15;
    // B loader: 2 threads per row
    const int brow  = tid >> 1;         // 0..127
    const int bhalf = tid & 1;

    // ldmatrix geometry (16B-unit XOR swizzle on 128B rows)
    const int arow  = wm*32 + (lane & 15);                        // 0..63
    const int axor  = arow & 7;
    const int asel  = lane >> 4;
    const int browl = 8*ng + (lane & 7) + 32*((lane >> 4) & 1);   // 0..63
    const int bxor  = lane & 7;
    const int bsel  = (lane >> 3) & 1;

    float acc[2][4][4];
#pragma unroll
    for (int im = 0; im < 2; im++)
#pragma unroll
        for (int j = 0; j < 4; j++)
#pragma unroll
            for (int c = 0; c < 4; c++) acc[im][j][c] = 0.f;

    float rF[16];     // raw fp32 A (loaded iter i, converted end of iter i)
    uint2 rH[4];      // packed fp16 A (STS'd top of iter i+1)

    auto ldgF = [&](int i) {
        const int k  = kof(g, i);
        const int a0 = (i & 7) << 6;
#pragma unroll
        for (int jj = 0; jj < 4; jj++) {
            const int grow = s0 + rowgrp + 16*jj;
            float4 v = *reinterpret_cast<const float4*>(
                A + ((size_t)k*1024 + grow)*512 + a0 + lane16*4);
            rF[4*jj+0] = v.x; rF[4*jj+1] = v.y; rF[4*jj+2] = v.z; rF[4*jj+3] = v.w;
        }
    };
    auto cvtA = [&]() {
#pragma unroll
        for (int jj = 0; jj < 4; jj++)
            rH[jj] = make_uint2(packh(rF[4*jj+0], rF[4*jj+1]),
                                packh(rF[4*jj+2], rF[4*jj+3]));
    };
    auto stsA = [&](int buf) {
        const int unit = lane16 >> 1;
        const int sub  = (lane16 & 1) * 8;
#pragma unroll
        for (int jj = 0; jj < 4; jj++) {
            const int row = rowgrp + 16*jj;
            *reinterpret_cast<uint2*>(smem + buf*ATILE + row*128 +
                                      ((unit ^ (row & 7)) << 4) + sub) = rH[jj];
        }
    };
    auto cpB = [&](int i, int buf) {
        const int k  = kof(g, i);
        const int a0 = (i & 7) << 6;
        const __half* src = g_Uf + (size_t)(brow + 128 - k)*512 + a0;
        const uint32_t dst = smb + BOFF0 + buf*BTILE + brow*128;
        const int rx = brow & 7;
#pragma unroll
        for (int c = 0; c < 4; c++) {
            const int u = bhalf*4 + c;
            cpa16(dst + ((u ^ rx) << 4), src + u*8);
        }
    };

    // ---- prologue ----
    cpB(0, 0); asm volatile("cp.async.commit_group;" ::: "memory");
    cpB(1, 1); asm volatile("cp.async.commit_group;" ::: "memory");
    ldgF(0); cvtA(); stsA(0);
    ldgF(1); cvtA();

    // ---- main loop (NIT iterations, K=64 each) ----
    for (int i = 0; i < NIT; i++) {
        const int abuf = i & 1;
        const int bbuf = i % 3;
        const int k    = kof(g, i);

        if (i < NIT-1) asm volatile("cp.async.wait_group 1;" ::: "memory");
        else           asm volatile("cp.async.wait_group 0;" ::: "memory");
        __syncthreads();

        if (i + 1 < NIT) stsA((i + 1) & 1);
        if (i + 2 < NIT) {
            ldgF(i + 2);
            cpB(i + 2, (i + 2) % 3);
            asm volatile("cp.async.commit_group;" ::: "memory");
        }

        // causal liveness: n8-tile j covers n in [(4j+ng)*8, +8)
        bool lv[4];
#pragma unroll
        for (int j = 0; j < 4; j++)
            lv[j] = (k < ((4*j + ng) << 3) + 8);
        bool lp[2];
#pragma unroll
        for (int p = 0; p < 2; p++)
            lp[p] = lv[2*p + 1];      // lv monotone increasing in j

        const uint32_t ab = smb + abuf*ATILE + arow*128;
        const uint32_t bb = smb + BOFF0 + bbuf*BTILE + browl*128;
#pragma unroll
        for (int kb = 0; kb < 4; kb++) {
            uint32_t ah[2][4], uf[2][4];
            const int au = 2*kb + asel;
            ldmx4(ah[0], ab +        ((au ^ axor) << 4));
            ldmx4(ah[1], ab + 2048 + ((au ^ axor) << 4));
            const int bu = 2*kb + bsel;
            const uint32_t bsw = (uint32_t)((bu ^ bxor) << 4);
#pragma unroll
            for (int p = 0; p < 2; p++)
                if (lp[p]) ldmx4(uf[p], bb + p*8192 + bsw);
#pragma unroll
            for (int im = 0; im < 2; im++)
#pragma unroll
                for (int j = 0; j < 4; j++)
                    if (lv[j]) mma16816(acc[im][j], ah[im], &uf[j >> 1][(j & 1) * 2]);
        }

        if (i + 2 < NIT) cvtA();
    }

    // ---- epilogue: write split-K partials [g][t][s] ----
    float* pb = g_partial + (size_t)g * 131072;
    const int sidx = s0 + wm*32 + (lane >> 2);
#pragma unroll
    for (int im = 0; im < 2; im++) {
        const int sr = sidx + im*16;
#pragma unroll
        for (int j = 0; j < 4; j++) {
            const int n = ((4*j + ng) << 3) + (lane & 3) * 2;
            pb[(size_t)n      * 1024 + sr]     = acc[im][j][0];
            pb[(size_t)(n+1)  * 1024 + sr]     = acc[im][j][1];
            pb[(size_t)n      * 1024 + sr + 8] = acc[im][j][2];
            pb[(size_t)(n+1)  * 1024 + sr + 8] = acc[im][j][3];
        }
    }
}

__global__ __launch_bounds__(256) void reduce_kernel(float* __restrict__ out)
{
    int i = blockIdx.x*256 + threadIdx.x;   // 0..131071 floats
    float s = 0.f;
#pragma unroll
    for (int gg = 0; gg < KSPLIT; gg++)
        s += g_partial[(size_t)gg*131072 + i];
    out[i] = s;
}

extern "C" void kernel_launch(void* const* d_in, const int* in_sizes, int n_in,
                              void* d_out, int out_size)
{
    const float* us = (const float*)d_in[0];   // [128, 512]
    const float* A  = (const float*)d_in[1];   // [128, 1024, 512]
    if (n_in >= 2 && in_sizes[0] > in_sizes[1]) {
        const float* t = us; us = A; A = t;
    }
    cudaFuncSetAttribute(mma_kernel, cudaFuncAttributeMaxDynamicSharedMemorySize, SMEMT);

    prep_kernel<<<512, 256>>>(us);
    dummy_kernel<<<1, 1>>>();
    dummy_kernel<<<1, 1>>>();
    mma_kernel<<<dim3(16, KSPLIT), 256, SMEMT>>>(A);
    reduce_kernel<<<512, 256>>>((float*)d_out);
}